// round 13
// baseline (speedup 1.0000x reference)
#include <cuda_runtime.h>
#include <cuda_fp16.h>
#include <math.h>

#define BATCH 4096
__device__ float g_feat[BATCH * 192];
// prepped fp16 weights: [c][k_lin], k_lin = tap*VPAD + v  (96 x 256 each)
__device__ __half g_wP[96 * 256], g_wL[96 * 256];

typedef unsigned int u32;

__device__ __forceinline__ u32 sm32(const void* p) {
    u32 a;
    asm("{ .reg .u64 t; cvta.to.shared.u64 t, %1; cvt.u32.u64 %0, t; }"
        : "=r"(a) : "l"(p));
    return a;
}
__device__ __forceinline__ void ldsm4(u32* r, u32 a) {
    asm volatile("ldmatrix.sync.aligned.m8n8.x4.shared.b16 {%0,%1,%2,%3}, [%4];"
                 : "=r"(r[0]), "=r"(r[1]), "=r"(r[2]), "=r"(r[3]) : "r"(a));
}
__device__ __forceinline__ void mma16816(float* d, const u32* a, u32 b0, u32 b1) {
    asm volatile(
        "mma.sync.aligned.m16n8k16.row.col.f32.f16.f16.f32 "
        "{%0,%1,%2,%3}, {%4,%5,%6,%7}, {%8,%9}, {%0,%1,%2,%3};"
        : "+f"(d[0]), "+f"(d[1]), "+f"(d[2]), "+f"(d[3])
        : "r"(a[0]), "r"(a[1]), "r"(a[2]), "r"(a[3]), "r"(b0), "r"(b1));
}
template <int BYTES>
__device__ __forceinline__ void cpB(u32 dst, const void* src) {
    asm volatile("cp.async.ca.shared.global [%0], [%1], %2;"
                 :: "r"(dst), "l"(src), "n"(BYTES));
}
__device__ __forceinline__ void cp_commit() {
    asm volatile("cp.async.commit_group;" ::: "memory");
}
__device__ __forceinline__ void cp_wait0() {
    asm volatile("cp.async.wait_group 0;" ::: "memory");
}

// ---------------------------------------------------------------------------
// weight prep: fp32 [96][VU][TAPS] -> fp16 [96][256], k_lin = tap*VPAD + v
// ---------------------------------------------------------------------------
template <int VU, int TAPS, int VPAD, bool PRO>
__global__ void prep_w(const float* __restrict__ w) {
    int u = blockIdx.x * 256 + threadIdx.x;
    if (u >= 96 * 256) return;
    int c = u >> 8, k = u & 255;
    int tap = k / VPAD, v = k - tap * VPAD;
    float val = (v < VU) ? w[(c * VU + v) * TAPS + tap] : 0.f;
    (PRO ? g_wP : g_wL)[u] = __float2half_rn(val);
}

__global__ void zero_feat_kernel() {
    int i = blockIdx.x * 1024 + threadIdx.x;
    if (i < BATCH * 192) g_feat[i] = 0.f;
}

// ---------------------------------------------------------------------------
// Persistent conv via mma.sync m16n8k16 fp16 (x, w fp16; rel_err ~4e-5).
// 512 thr = 16 warps = 2 channel-groups (grp = wid/8, 48 ch each, NCF=6) x
// 8 position-warps; sect = (wid&7)/SW selects the sample section; each warp
// owns 32 positions (MW=2). Deferred epilogue: per-lane raw max in 12 regs
// across the CTA's CONTIGUOUS tile range, flushed on sample change only.
// Staging: CPB=16 keeps the cp.async op count under the tensor time (r12:
// ligand at CPB=8 was LSU-issue-bound at ~12.8k cyc/SMSP vs 6.1k tensor).
//   VMAJ=true : SPITCH=ROWS (16B-aligned dsts); cvt v-major -> conflict-free
//               loads, 4-way stores (tolerated; see protein r10/r12).
//   VMAJ=false: CPB=8 path, SPITCH=ROWS+2, r-major cvt (unused this round).
// ---------------------------------------------------------------------------
template <int VU, int VPAD, int CHK, int TAPS, int LEN, int OUT, int SECT,
          int NSAMP, int NTPER, int FEAT_OFF, int XSTR, int CPB, bool VMAJ,
          bool PRO>
__global__ __launch_bounds__(512, 1)
void conv_mma(const float* __restrict__ x, const float* __restrict__ bias)
{
    constexpr int NTH   = 512;
    constexpr int NCF   = 6;                      // n8 channel-frags per warp
    constexpr int MW    = 2;
    constexpr int SW    = 8 / NSAMP;              // warps per section
    constexpr int TILE  = SW * 32;                // positions per section
    constexpr int ROWS  = NSAMP * SECT;
    constexpr int XROWS = ROWS + 8;               // zeroed halo rows
    constexpr int WSTR  = VPAD * TAPS * 2 + 16;   // 528
    constexpr int OFF_W = 0;
    constexpr int OFF_X = 96 * WSTR;              // 50688
    constexpr int XBUF  = XROWS * XSTR;
    constexpr int OFF_S = OFF_X + 2 * XBUF;       // fp32 scratch
    constexpr int SPITCH = VMAJ ? ROWS : ((ROWS + 2) & ~1);
    constexpr int OFF_B = OFF_S + VU * SPITCH * 4;
    constexpr int NTILES = (NSAMP == 2) ? BATCH / 2 : BATCH * NTPER;
    constexpr int CELEM = CPB / 4;                // floats per cp chunk
    constexpr int NCHK  = SECT / CELEM;           // chunks per (v, s)
    constexpr int TOTC  = VU * NSAMP * NCHK;
    constexpr int NCP   = (TOTC + NTH - 1) / NTH;
    constexpr int TOTV  = VU * ROWS;
    constexpr int NCV   = (TOTV + NTH - 1) / NTH;

    extern __shared__ char sm[];
    const u32 sb  = sm32(sm);
    const int tid = threadIdx.x, wid = tid >> 5, lane = tid & 31;
    const int grp = wid >> 3, w7 = wid & 7;
    const int sect = w7 / SW, slot = w7 % SW;

    const __half* wsrc = PRO ? g_wP : g_wL;
    for (int u = tid; u < 96 * 256; u += NTH) {
        int c = u >> 8, k = u & 255;
        *(__half*)(sm + OFF_W + c * WSTR + k * 2) = wsrc[u];
    }
    // zero x region once (covers vocab pad bytes inside rows + halo rows)
    for (int u = tid; u < (2 * XBUF) / 16; u += NTH)
        *reinterpret_cast<float4*>(sm + OFF_X + u * 16) =
            make_float4(0.f, 0.f, 0.f, 0.f);
    if (tid < 96) ((float*)(sm + OFF_B))[tid] = bias[tid];

    // contiguous tile range for this CTA
    constexpr int TPC = (NTILES + 147) / 148;
    const int gbeg = blockIdx.x * TPC;
    const int gend = (gbeg + TPC < NTILES) ? gbeg + TPC : NTILES;
    if (gbeg >= gend) return;    // uniform per CTA

    auto issue_cp = [&](int g) {
        int b0 = (NSAMP == 2) ? 2 * g : g / NTPER;
        int t0 = (NSAMP == 2) ? 0 : (g - b0 * NTPER) * TILE;
        int valid = LEN - t0; if (valid > SECT) valid = SECT;
        int nch = valid / CELEM;
        #pragma unroll
        for (int i = 0; i < NCP; i++) {
            int u = tid + i * NTH;
            if (u < TOTC) {
                int v = u / (NSAMP * NCHK);
                int rem = u - v * (NSAMP * NCHK);
                int s = rem / NCHK, c = rem - s * NCHK;
                if (c < nch)
                    cpB<CPB>(sb + (u32)(OFF_S +
                                 (v * SPITCH + s * SECT + c * CELEM) * 4),
                             x + ((size_t)(b0 + s) * VU + v) * LEN
                               + t0 + c * CELEM);
            }
        }
        cp_commit();
    };
    auto cvt = [&](int g, int nb) {
        int b0 = (NSAMP == 2) ? 2 * g : g / NTPER;
        int t0 = (NSAMP == 2) ? 0 : (g - b0 * NTPER) * TILE;
        int valid = LEN - t0; if (valid > SECT) valid = SECT;
        const float* sc = (const float*)(sm + OFF_S);
        char* xp = sm + OFF_X + nb * XBUF;
        #pragma unroll
        for (int i = 0; i < NCV; i++) {
            int u = tid + i * NTH;
            if (u < TOTV) {
                int v, r;
                if (VMAJ) { v = u / ROWS; r = u - v * ROWS; }   // tid -> r
                else      { r = u / VU;   v = u - r * VU;   }   // tid -> v
                int rr = r % SECT;
                float val = (rr < valid) ? sc[v * SPITCH + r] : 0.f;
                *(__half*)(xp + r * XSTR + v * 2) = __float2half_rn(val);
            }
        }
    };

    issue_cp(gbeg);
    cp_wait0();
    __syncthreads();
    cvt(gbeg, 0);
    __syncthreads();

    const u32 a_lo = (u32)((lane & 15) * XSTR + (lane >> 4) * 16);
    const u32 b_lo = (u32)(((lane & 7) + ((lane >> 4) << 3)) * WSTR
                           + ((lane >> 3) & 1) * 16);
    const u32 wb = sb + (u32)OFF_W + b_lo + (u32)(grp * 48 * WSTR);
    const int prow = sect * SECT + slot * 32;
    const float NEG = -1e30f;

    float mxv[12];
    #pragma unroll
    for (int q = 0; q < 12; q++) mxv[q] = NEG;

    auto flush = [&](int b) {
        #pragma unroll
        for (int off = 4; off <= 16; off <<= 1)
            #pragma unroll
            for (int q = 0; q < 12; q++)
                mxv[q] = fmaxf(mxv[q], __shfl_xor_sync(0xffffffffu, mxv[q], off));
        if (lane < 4) {
            #pragma unroll
            for (int j = 0; j < NCF; j++)
                #pragma unroll
                for (int e = 0; e < 2; e++) {
                    int c = grp * 48 + j * 8 + lane * 2 + e;
                    float bb = ((const float*)(sm + OFF_B))[c];
                    float val = fmaxf(mxv[2 * j + e] + bb, 0.f);
                    atomicMax(reinterpret_cast<int*>(
                                  &g_feat[(size_t)b * 192 + FEAT_OFF + c]),
                              __float_as_int(val));
                }
        }
        #pragma unroll
        for (int q = 0; q < 12; q++) mxv[q] = NEG;
    };

    int buf = 0;
    for (int g = gbeg; g < gend; ++g) {
        const int gn = g + 1;
        if (gn < gend) issue_cp(gn);     // async: overlaps the mma loop

        float acc[MW][NCF][4];
        #pragma unroll
        for (int m = 0; m < MW; m++)
            #pragma unroll
            for (int j = 0; j < NCF; j++)
                #pragma unroll
                for (int e = 0; e < 4; e++) acc[m][j][e] = 0.f;

        const u32 xab = sb + (u32)(OFF_X + buf * XBUF)
                      + (u32)prow * XSTR + a_lo;

        #pragma unroll
        for (int tap = 0; tap < TAPS; tap++) {
            #pragma unroll
            for (int ch = 0; ch < CHK; ch++) {
                const u32 aoff = (u32)(tap * XSTR + ch * 32);
                u32 ah[MW][4];
                #pragma unroll
                for (int m = 0; m < MW; m++)
                    ldsm4(ah[m], xab + aoff + (u32)(m * 16 * XSTR));
                const u32 wk = (u32)((tap * VPAD + ch * 16) * 2);
                #pragma unroll
                for (int p = 0; p < NCF / 2; p++) {
                    u32 bf[4];
                    ldsm4(bf, wb + (u32)(p * 16 * WSTR) + wk);
                    #pragma unroll
                    for (int m = 0; m < MW; m++) {
                        mma16816(acc[m][2 * p],     ah[m], bf[0], bf[1]);
                        mma16816(acc[m][2 * p + 1], ah[m], bf[2], bf[3]);
                    }
                }
            }
        }

        // ---- accumulate masked max into persistent regs; flush on b change
        {
            const int b0 = (NSAMP == 2) ? 2 * g : g / NTPER;
            const int t0 = (NSAMP == 2) ? 0 : (g - b0 * NTPER) * TILE;
            const int b  = b0 + ((NSAMP == 2) ? sect : 0);
            const int pb = ((NSAMP == 2) ? 0 : t0) + slot * 32;
            const int row = lane >> 2;
            #pragma unroll
            for (int m = 0; m < MW; m++) {
                const int p0 = pb + m * 16 + row;
                #pragma unroll
                for (int j = 0; j < NCF; j++)
                    #pragma unroll
                    for (int e = 0; e < 2; e++) {
                        float v = mxv[2 * j + e];
                        if (p0 < OUT)     v = fmaxf(v, acc[m][j][e]);
                        if (p0 + 8 < OUT) v = fmaxf(v, acc[m][j][e + 2]);
                        mxv[2 * j + e] = v;
                    }
            }
            bool bchange = (NSAMP == 2) || (gn >= gend)
                         || (gn / NTPER != g / NTPER);
            if (bchange) flush(b);
        }

        cp_wait0();
        __syncthreads();                 // all mma reads of buf done; scratch ready
        if (gn < gend) cvt(gn, buf ^ 1);
        __syncthreads();                 // buf^1 visible before next mma
        buf ^= 1;
    }
}

// ---------------------------------------------------------------------------
// Per-sample: x = feat.reshape(6,32); gram = x^T x; L2-normalize; dot w_aff.
// ---------------------------------------------------------------------------
__global__ __launch_bounds__(256)
void gram_readout_kernel(const float* __restrict__ w_aff,
                         const float* __restrict__ b_aff,
                         float* __restrict__ out, int B)
{
    __shared__ float s_w[1024];
    __shared__ float s_f[8][192];
    const int tid  = threadIdx.x;
    const int warp = tid >> 5, lane = tid & 31;
    const int b = blockIdx.x * 8 + warp;

    for (int u = tid; u < 1024; u += 256) s_w[u] = w_aff[u];
    if (b < B)
        for (int u = lane; u < 192; u += 32) s_f[warp][u] = g_feat[(size_t)b * 192 + u];
    __syncthreads();
    if (b >= B) return;

    float xk[6];
    #pragma unroll
    for (int i = 0; i < 6; i++) xk[i] = s_f[warp][i * 32 + lane];

    float s1 = 0.f, s2 = 0.f;
    #pragma unroll 4
    for (int j = 0; j < 32; j++) {
        float g = 0.f;
        #pragma unroll
        for (int i = 0; i < 6; i++) g = fmaf(s_f[warp][i * 32 + j], xk[i], g);
        s2 = fmaf(g, g, s2);
        s1 = fmaf(g, s_w[j * 32 + lane], s1);
    }
    #pragma unroll
    for (int off = 16; off > 0; off >>= 1) {
        s1 += __shfl_xor_sync(0xffffffffu, s1, off);
        s2 += __shfl_xor_sync(0xffffffffu, s2, off);
    }
    if (lane == 0) out[b] = s1 / (sqrtf(s2) + 1e-12f) + b_aff[0];
}

// ---------------------------------------------------------------------------

extern "C" void kernel_launch(void* const* d_in, const int* in_sizes, int n_in,
                              void* d_out, int out_size)
{
    const float* protein = (const float*)d_in[0];
    const float* ligand  = (const float*)d_in[1];
    const float* w_pro   = (const float*)d_in[2];
    const float* b_pro   = (const float*)d_in[3];
    const float* w_lig   = (const float*)d_in[4];
    const float* b_lig   = (const float*)d_in[5];
    const float* w_aff   = (const float*)d_in[6];
    const float* b_aff   = (const float*)d_in[7];

    int seen96 = 0;
    for (int i = 0; i < n_in; i++) {
        long long s = in_sizes[i];
        const float* p = (const float*)d_in[i];
        if      (s == (long long)BATCH * 25 * 1000) protein = p;
        else if (s == (long long)BATCH * 64 * 100)  ligand  = p;
        else if (s == 96LL * 25 * 8)                w_pro   = p;
        else if (s == 96LL * 64 * 4)                w_lig   = p;
        else if (s == 1024LL)                       w_aff   = p;
        else if (s == 96LL) { if (seen96++ == 0) b_pro = p; else b_lig = p; }
        else if (s == 1LL)                          b_aff   = p;
    }

    float* out = (float*)d_out;

    // ligand : NSAMP=2 SECT=128, CPB=16, v-major cvt, SPITCH=256 (cp halved)
    // protein: NSAMP=1 SECT=264 NTPER=4, CPB=16, v-major cvt (r12, unchanged)
    auto kL = conv_mma<64, 64, 4, 4, 100, 97, 128, 2, 1, 0, 144, 16, true, false>;
    auto kP = conv_mma<25, 32, 2, 8, 1000, 993, 264, 1, 4, 96, 80, 16, true,  true>;

    // smem sizes (mirror kernel constexprs: OFF_B + 96 floats)
    constexpr int SMEM_L = 50688 + 2 * (264 * 144) + 64 * 256 * 4 + 384; // 192640
    constexpr int SMEM_P = 50688 + 2 * (272 * 80)  + 25 * 264 * 4 + 384; // 120992

    cudaFuncSetAttribute(kL, cudaFuncAttributeMaxDynamicSharedMemorySize, SMEM_L);
    cudaFuncSetAttribute(kP, cudaFuncAttributeMaxDynamicSharedMemorySize, SMEM_P);

    zero_feat_kernel<<<(BATCH * 192 + 1023) / 1024, 1024>>>();
    prep_w<64, 4, 64, false><<<96, 256>>>(w_lig);
    prep_w<25, 8, 32, true><<<96, 256>>>(w_pro);
    kL<<<148, 512, SMEM_L>>>(ligand, b_lig);
    kP<<<148, 512, SMEM_P>>>(protein, b_pro);
    gram_readout_kernel<<<BATCH / 8, 256>>>(w_aff, b_aff, out, BATCH);
}

// round 14
// speedup vs baseline: 1.0255x; 1.0255x over previous
#include <cuda_runtime.h>
#include <cuda_fp16.h>
#include <math.h>

#define BATCH 4096
__device__ float g_feat[BATCH * 192];
// prepped fp16 weights: [c][k_lin], k_lin = tap*VPAD + v  (96 x 256 each)
__device__ __half g_wP[96 * 256], g_wL[96 * 256];

typedef unsigned int u32;

__device__ __forceinline__ u32 sm32(const void* p) {
    u32 a;
    asm("{ .reg .u64 t; cvta.to.shared.u64 t, %1; cvt.u32.u64 %0, t; }"
        : "=r"(a) : "l"(p));
    return a;
}
__device__ __forceinline__ void ldsm4(u32* r, u32 a) {
    asm volatile("ldmatrix.sync.aligned.m8n8.x4.shared.b16 {%0,%1,%2,%3}, [%4];"
                 : "=r"(r[0]), "=r"(r[1]), "=r"(r[2]), "=r"(r[3]) : "r"(a));
}
__device__ __forceinline__ void mma16816(float* d, const u32* a, u32 b0, u32 b1) {
    asm volatile(
        "mma.sync.aligned.m16n8k16.row.col.f32.f16.f16.f32 "
        "{%0,%1,%2,%3}, {%4,%5,%6,%7}, {%8,%9}, {%0,%1,%2,%3};"
        : "+f"(d[0]), "+f"(d[1]), "+f"(d[2]), "+f"(d[3])
        : "r"(a[0]), "r"(a[1]), "r"(a[2]), "r"(a[3]), "r"(b0), "r"(b1));
}
template <int BYTES>
__device__ __forceinline__ void cpB(u32 dst, const void* src) {
    asm volatile("cp.async.ca.shared.global [%0], [%1], %2;"
                 :: "r"(dst), "l"(src), "n"(BYTES));
}
__device__ __forceinline__ void cp_commit() {
    asm volatile("cp.async.commit_group;" ::: "memory");
}
__device__ __forceinline__ void cp_wait0() {
    asm volatile("cp.async.wait_group 0;" ::: "memory");
}

// ---------------------------------------------------------------------------
// weight prep: fp32 [96][VU][TAPS] -> fp16 [96][256], k_lin = tap*VPAD + v
// ---------------------------------------------------------------------------
template <int VU, int TAPS, int VPAD, bool PRO>
__global__ void prep_w(const float* __restrict__ w) {
    int u = blockIdx.x * 256 + threadIdx.x;
    if (u >= 96 * 256) return;
    int c = u >> 8, k = u & 255;
    int tap = k / VPAD, v = k - tap * VPAD;
    float val = (v < VU) ? w[(c * VU + v) * TAPS + tap] : 0.f;
    (PRO ? g_wP : g_wL)[u] = __float2half_rn(val);
}

__global__ void zero_feat_kernel() {
    int i = blockIdx.x * 1024 + threadIdx.x;
    if (i < BATCH * 192) g_feat[i] = 0.f;
}

// ---------------------------------------------------------------------------
// Persistent conv via mma.sync m16n8k16 fp16 (x, w fp16; rel_err ~4e-5).
// NTH threads = NW warps = 2 channel-groups (grp, 48 ch each, NCF=6) x NPW
// position-warps; sect = w/SW selects the sample section (SW = NPW/NSAMP);
// each warp owns 32 positions (MW=2). Deferred epilogue: per-lane raw max
// in 12 regs across the CTA's CONTIGUOUS tile range, flushed on sample
// change only. Staging styles (per-branch tuned, r10-r13 post-mortems):
//   VMAJ=true : CPB=16, SPITCH=ROWS; cvt v-major (conflict-free loads).
//   VMAJ=false: CPB=8, SPITCH=ROWS+2 (2*odd); cvt r-major (cf stores).
// NTH=256 + MAXCTA=2 gives two independent CTAs/SM: same 4 warps/SMSP but
// desynchronized barriers/epilogues overlap each other's mma.
// ---------------------------------------------------------------------------
template <int NTH, int GRID, int VU, int VPAD, int CHK, int TAPS, int LEN,
          int OUT, int SECT, int NSAMP, int NTPER, int FEAT_OFF, int XSTR,
          int CPB, bool VMAJ, bool PRO>
__global__ __launch_bounds__(NTH, NTH == 256 ? 2 : 1)
void conv_mma(const float* __restrict__ x, const float* __restrict__ bias)
{
    constexpr int NW    = NTH / 32;
    constexpr int NPW   = NW / 2;                 // position-warps per group
    constexpr int NCF   = 6;                      // n8 channel-frags per warp
    constexpr int MW    = 2;
    constexpr int SW    = NPW / NSAMP;            // warps per section
    constexpr int TILE  = SW * 32;                // positions per section
    constexpr int ROWS  = NSAMP * SECT;
    constexpr int XROWS = ROWS + 8;               // zeroed halo rows
    constexpr int WSTR  = VPAD * TAPS * 2 + 16;   // 528
    constexpr int OFF_W = 0;
    constexpr int OFF_X = 96 * WSTR;              // 50688
    constexpr int XBUF  = XROWS * XSTR;
    constexpr int OFF_S = OFF_X + 2 * XBUF;       // fp32 scratch
    constexpr int SPITCH = VMAJ ? ROWS : ((ROWS + 2) & ~1);
    constexpr int OFF_B = OFF_S + VU * SPITCH * 4;
    constexpr int NTILES = (NSAMP == 2) ? BATCH / 2 : BATCH * NTPER;
    constexpr int CELEM = CPB / 4;                // floats per cp chunk
    constexpr int NCHK  = SECT / CELEM;           // chunks per (v, s)
    constexpr int TOTC  = VU * NSAMP * NCHK;
    constexpr int NCP   = (TOTC + NTH - 1) / NTH;
    constexpr int TOTV  = VU * ROWS;
    constexpr int NCV   = (TOTV + NTH - 1) / NTH;

    extern __shared__ char sm[];
    const u32 sb  = sm32(sm);
    const int tid = threadIdx.x, wid = tid >> 5, lane = tid & 31;
    const int grp = wid / NPW, w = wid - grp * NPW;
    const int sect = w / SW, slot = w - sect * SW;

    const __half* wsrc = PRO ? g_wP : g_wL;
    for (int u = tid; u < 96 * 256; u += NTH) {
        int c = u >> 8, k = u & 255;
        *(__half*)(sm + OFF_W + c * WSTR + k * 2) = wsrc[u];
    }
    // zero x region once (covers vocab pad bytes inside rows + halo rows)
    for (int u = tid; u < (2 * XBUF) / 16; u += NTH)
        *reinterpret_cast<float4*>(sm + OFF_X + u * 16) =
            make_float4(0.f, 0.f, 0.f, 0.f);
    if (tid < 96) ((float*)(sm + OFF_B))[tid] = bias[tid];

    // contiguous tile range for this CTA
    constexpr int TPC = (NTILES + GRID - 1) / GRID;
    const int gbeg = blockIdx.x * TPC;
    const int gend = (gbeg + TPC < NTILES) ? gbeg + TPC : NTILES;
    if (gbeg >= gend) return;    // uniform per CTA

    auto issue_cp = [&](int g) {
        int b0 = (NSAMP == 2) ? 2 * g : g / NTPER;
        int t0 = (NSAMP == 2) ? 0 : (g - b0 * NTPER) * TILE;
        int valid = LEN - t0; if (valid > SECT) valid = SECT;
        int nch = valid / CELEM;
        #pragma unroll
        for (int i = 0; i < NCP; i++) {
            int u = tid + i * NTH;
            if (u < TOTC) {
                int v = u / (NSAMP * NCHK);
                int rem = u - v * (NSAMP * NCHK);
                int s = rem / NCHK, c = rem - s * NCHK;
                if (c < nch)
                    cpB<CPB>(sb + (u32)(OFF_S +
                                 (v * SPITCH + s * SECT + c * CELEM) * 4),
                             x + ((size_t)(b0 + s) * VU + v) * LEN
                               + t0 + c * CELEM);
            }
        }
        cp_commit();
    };
    auto cvt = [&](int g, int nb) {
        int b0 = (NSAMP == 2) ? 2 * g : g / NTPER;
        int t0 = (NSAMP == 2) ? 0 : (g - b0 * NTPER) * TILE;
        int valid = LEN - t0; if (valid > SECT) valid = SECT;
        const float* sc = (const float*)(sm + OFF_S);
        char* xp = sm + OFF_X + nb * XBUF;
        #pragma unroll
        for (int i = 0; i < NCV; i++) {
            int u = tid + i * NTH;
            if (u < TOTV) {
                int v, r;
                if (VMAJ) { v = u / ROWS; r = u - v * ROWS; }   // tid -> r
                else      { r = u / VU;   v = u - r * VU;   }   // tid -> v
                int rr = r % SECT;
                float val = (rr < valid) ? sc[v * SPITCH + r] : 0.f;
                *(__half*)(xp + r * XSTR + v * 2) = __float2half_rn(val);
            }
        }
    };

    issue_cp(gbeg);
    cp_wait0();
    __syncthreads();
    cvt(gbeg, 0);
    __syncthreads();

    const u32 a_lo = (u32)((lane & 15) * XSTR + (lane >> 4) * 16);
    const u32 b_lo = (u32)(((lane & 7) + ((lane >> 4) << 3)) * WSTR
                           + ((lane >> 3) & 1) * 16);
    const u32 wb = sb + (u32)OFF_W + b_lo + (u32)(grp * 48 * WSTR);
    const int prow = sect * SECT + slot * 32;
    const float NEG = -1e30f;

    float mxv[12];
    #pragma unroll
    for (int q = 0; q < 12; q++) mxv[q] = NEG;

    auto flush = [&](int b) {
        #pragma unroll
        for (int off = 4; off <= 16; off <<= 1)
            #pragma unroll
            for (int q = 0; q < 12; q++)
                mxv[q] = fmaxf(mxv[q], __shfl_xor_sync(0xffffffffu, mxv[q], off));
        if (lane < 4) {
            #pragma unroll
            for (int j = 0; j < NCF; j++)
                #pragma unroll
                for (int e = 0; e < 2; e++) {
                    int c = grp * 48 + j * 8 + lane * 2 + e;
                    float bb = ((const float*)(sm + OFF_B))[c];
                    float val = fmaxf(mxv[2 * j + e] + bb, 0.f);
                    atomicMax(reinterpret_cast<int*>(
                                  &g_feat[(size_t)b * 192 + FEAT_OFF + c]),
                              __float_as_int(val));
                }
        }
        #pragma unroll
        for (int q = 0; q < 12; q++) mxv[q] = NEG;
    };

    int buf = 0;
    for (int g = gbeg; g < gend; ++g) {
        const int gn = g + 1;
        if (gn < gend) issue_cp(gn);     // async: overlaps the mma loop

        float acc[MW][NCF][4];
        #pragma unroll
        for (int m = 0; m < MW; m++)
            #pragma unroll
            for (int j = 0; j < NCF; j++)
                #pragma unroll
                for (int e = 0; e < 4; e++) acc[m][j][e] = 0.f;

        const u32 xab = sb + (u32)(OFF_X + buf * XBUF)
                      + (u32)prow * XSTR + a_lo;

        #pragma unroll
        for (int tap = 0; tap < TAPS; tap++) {
            #pragma unroll
            for (int ch = 0; ch < CHK; ch++) {
                const u32 aoff = (u32)(tap * XSTR + ch * 32);
                u32 ah[MW][4];
                #pragma unroll
                for (int m = 0; m < MW; m++)
                    ldsm4(ah[m], xab + aoff + (u32)(m * 16 * XSTR));
                const u32 wk = (u32)((tap * VPAD + ch * 16) * 2);
                #pragma unroll
                for (int p = 0; p < NCF / 2; p++) {
                    u32 bf[4];
                    ldsm4(bf, wb + (u32)(p * 16 * WSTR) + wk);
                    #pragma unroll
                    for (int m = 0; m < MW; m++) {
                        mma16816(acc[m][2 * p],     ah[m], bf[0], bf[1]);
                        mma16816(acc[m][2 * p + 1], ah[m], bf[2], bf[3]);
                    }
                }
            }
        }

        // ---- accumulate masked max into persistent regs; flush on b change
        {
            const int b0 = (NSAMP == 2) ? 2 * g : g / NTPER;
            const int t0 = (NSAMP == 2) ? 0 : (g - b0 * NTPER) * TILE;
            const int b  = b0 + ((NSAMP == 2) ? sect : 0);
            const int pb = ((NSAMP == 2) ? 0 : t0) + slot * 32;
            const int row = lane >> 2;
            #pragma unroll
            for (int m = 0; m < MW; m++) {
                const int p0 = pb + m * 16 + row;
                #pragma unroll
                for (int j = 0; j < NCF; j++)
                    #pragma unroll
                    for (int e = 0; e < 2; e++) {
                        float v = mxv[2 * j + e];
                        if (p0 < OUT)     v = fmaxf(v, acc[m][j][e]);
                        if (p0 + 8 < OUT) v = fmaxf(v, acc[m][j][e + 2]);
                        mxv[2 * j + e] = v;
                    }
            }
            bool bchange = (NSAMP == 2) || (gn >= gend)
                         || (gn / NTPER != g / NTPER);
            if (bchange) flush(b);
        }

        cp_wait0();
        __syncthreads();                 // all mma reads of buf done; scratch ready
        if (gn < gend) cvt(gn, buf ^ 1);
        __syncthreads();                 // buf^1 visible before next mma
        buf ^= 1;
    }
}

// ---------------------------------------------------------------------------
// Per-sample: x = feat.reshape(6,32); gram = x^T x; L2-normalize; dot w_aff.
// ---------------------------------------------------------------------------
__global__ __launch_bounds__(256)
void gram_readout_kernel(const float* __restrict__ w_aff,
                         const float* __restrict__ b_aff,
                         float* __restrict__ out, int B)
{
    __shared__ float s_w[1024];
    __shared__ float s_f[8][192];
    const int tid  = threadIdx.x;
    const int warp = tid >> 5, lane = tid & 31;
    const int b = blockIdx.x * 8 + warp;

    for (int u = tid; u < 1024; u += 256) s_w[u] = w_aff[u];
    if (b < B)
        for (int u = lane; u < 192; u += 32) s_f[warp][u] = g_feat[(size_t)b * 192 + u];
    __syncthreads();
    if (b >= B) return;

    float xk[6];
    #pragma unroll
    for (int i = 0; i < 6; i++) xk[i] = s_f[warp][i * 32 + lane];

    float s1 = 0.f, s2 = 0.f;
    #pragma unroll 4
    for (int j = 0; j < 32; j++) {
        float g = 0.f;
        #pragma unroll
        for (int i = 0; i < 6; i++) g = fmaf(s_f[warp][i * 32 + j], xk[i], g);
        s2 = fmaf(g, g, s2);
        s1 = fmaf(g, s_w[j * 32 + lane], s1);
    }
    #pragma unroll
    for (int off = 16; off > 0; off >>= 1) {
        s1 += __shfl_xor_sync(0xffffffffu, s1, off);
        s2 += __shfl_xor_sync(0xffffffffu, s2, off);
    }
    if (lane == 0) out[b] = s1 / (sqrtf(s2) + 1e-12f) + b_aff[0];
}

// ---------------------------------------------------------------------------

extern "C" void kernel_launch(void* const* d_in, const int* in_sizes, int n_in,
                              void* d_out, int out_size)
{
    const float* protein = (const float*)d_in[0];
    const float* ligand  = (const float*)d_in[1];
    const float* w_pro   = (const float*)d_in[2];
    const float* b_pro   = (const float*)d_in[3];
    const float* w_lig   = (const float*)d_in[4];
    const float* b_lig   = (const float*)d_in[5];
    const float* w_aff   = (const float*)d_in[6];
    const float* b_aff   = (const float*)d_in[7];

    int seen96 = 0;
    for (int i = 0; i < n_in; i++) {
        long long s = in_sizes[i];
        const float* p = (const float*)d_in[i];
        if      (s == (long long)BATCH * 25 * 1000) protein = p;
        else if (s == (long long)BATCH * 64 * 100)  ligand  = p;
        else if (s == 96LL * 25 * 8)                w_pro   = p;
        else if (s == 96LL * 64 * 4)                w_lig   = p;
        else if (s == 1024LL)                       w_aff   = p;
        else if (s == 96LL) { if (seen96++ == 0) b_pro = p; else b_lig = p; }
        else if (s == 1LL)                          b_aff   = p;
    }

    float* out = (float*)d_out;

    // ligand : r12 config, unchanged (measured 98 us): 512thr, NSAMP=2,
    //          SECT=128, CPB=8, r-major cvt, grid 148
    // protein: 256thr x 2 CTAs/SM (grid 296), TILE=128, NTPER=8, SECT=136,
    //          CPB=16, v-major cvt, deferred flush per sample
    auto kL = conv_mma<512, 148, 64, 64, 4, 4, 100, 97, 128, 2, 1, 0, 144,
                       8, false, false>;
    auto kP = conv_mma<256, 296, 25, 32, 2, 8, 1000, 993, 136, 1, 8, 96, 80,
                       16, true, true>;

    // smem sizes (mirror kernel constexprs: OFF_B + 96 floats)
    constexpr int SMEM_L = 50688 + 2 * (264 * 144) + 64 * 258 * 4 + 384; // 193152
    constexpr int SMEM_P = 50688 + 2 * (144 * 80)  + 25 * 136 * 4 + 384; // 87712

    cudaFuncSetAttribute(kL, cudaFuncAttributeMaxDynamicSharedMemorySize, SMEM_L);
    cudaFuncSetAttribute(kP, cudaFuncAttributeMaxDynamicSharedMemorySize, SMEM_P);

    zero_feat_kernel<<<(BATCH * 192 + 1023) / 1024, 1024>>>();
    prep_w<64, 4, 64, false><<<96, 256>>>(w_lig);
    prep_w<25, 8, 32, true><<<96, 256>>>(w_pro);
    kL<<<148, 512, SMEM_L>>>(ligand, b_lig);
    kP<<<296, 256, SMEM_P>>>(protein, b_pro);
    gram_readout_kernel<<<BATCH / 8, 256>>>(w_aff, b_aff, out, BATCH);
}

// round 15
// speedup vs baseline: 1.0455x; 1.0195x over previous
#include <cuda_runtime.h>
#include <cuda_fp16.h>
#include <math.h>

#define BATCH 4096
__device__ float g_feat[BATCH * 192];
// prepped fp16 weights: [c][k_lin], k_lin = tap*VPAD + v  (96 x 256 each)
__device__ __half g_wP[96 * 256], g_wL[96 * 256];

typedef unsigned int u32;

__device__ __forceinline__ u32 sm32(const void* p) {
    u32 a;
    asm("{ .reg .u64 t; cvta.to.shared.u64 t, %1; cvt.u32.u64 %0, t; }"
        : "=r"(a) : "l"(p));
    return a;
}
__device__ __forceinline__ void ldsm4(u32* r, u32 a) {
    asm volatile("ldmatrix.sync.aligned.m8n8.x4.shared.b16 {%0,%1,%2,%3}, [%4];"
                 : "=r"(r[0]), "=r"(r[1]), "=r"(r[2]), "=r"(r[3]) : "r"(a));
}
__device__ __forceinline__ void mma16816(float* d, const u32* a, u32 b0, u32 b1) {
    asm volatile(
        "mma.sync.aligned.m16n8k16.row.col.f32.f16.f16.f32 "
        "{%0,%1,%2,%3}, {%4,%5,%6,%7}, {%8,%9}, {%0,%1,%2,%3};"
        : "+f"(d[0]), "+f"(d[1]), "+f"(d[2]), "+f"(d[3])
        : "r"(a[0]), "r"(a[1]), "r"(a[2]), "r"(a[3]), "r"(b0), "r"(b1));
}
// --- sm_90-baseline bulk copy + mbarrier (legal on plain sm_100) ---
__device__ __forceinline__ void mbar_init(u32 mbar, u32 cnt) {
    asm volatile("mbarrier.init.shared.b64 [%0], %1;" :: "r"(mbar), "r"(cnt)
                 : "memory");
}
__device__ __forceinline__ void mbar_expect_tx(u32 mbar, u32 bytes) {
    asm volatile("mbarrier.arrive.expect_tx.shared.b64 _, [%0], %1;"
                 :: "r"(mbar), "r"(bytes) : "memory");
}
__device__ __forceinline__ void bulk_g2s(u32 dst, const void* src, u32 bytes,
                                         u32 mbar) {
    asm volatile(
        "cp.async.bulk.shared::cluster.global.mbarrier::complete_tx::bytes "
        "[%0], [%1], %2, [%3];"
        :: "r"(dst), "l"(src), "r"(bytes), "r"(mbar) : "memory");
}
__device__ __forceinline__ void mbar_wait(u32 mbar, u32 parity) {
    asm volatile(
        "{ .reg .pred P;\n"
        "WAITLP%=:\n"
        " mbarrier.try_wait.parity.acquire.cta.shared::cta.b64 P, [%0], %1, 0x989680;\n"
        " @P bra.uni WDONE%=;\n"
        " bra.uni WAITLP%=;\n"
        "WDONE%=: }"
        :: "r"(mbar), "r"(parity) : "memory");
}

// ---------------------------------------------------------------------------
// weight prep: fp32 [96][VU][TAPS] -> fp16 [96][256], k_lin = tap*VPAD + v
// ---------------------------------------------------------------------------
template <int VU, int TAPS, int VPAD, bool PRO>
__global__ void prep_w(const float* __restrict__ w) {
    int u = blockIdx.x * 256 + threadIdx.x;
    if (u >= 96 * 256) return;
    int c = u >> 8, k = u & 255;
    int tap = k / VPAD, v = k - tap * VPAD;
    float val = (v < VU) ? w[(c * VU + v) * TAPS + tap] : 0.f;
    (PRO ? g_wP : g_wL)[u] = __float2half_rn(val);
}

__global__ void zero_feat_kernel() {
    int i = blockIdx.x * 1024 + threadIdx.x;
    if (i < BATCH * 192) g_feat[i] = 0.f;
}

// ---------------------------------------------------------------------------
// Persistent conv via mma.sync m16n8k16 fp16 (x, w fp16; rel_err ~4e-5).
// NTH threads = NW warps = 2 channel-groups (grp, 48 ch each, NCF=6) x NPW
// position-warps; sect = w/SW selects the sample section (SW = NPW/NSAMP);
// each warp owns 32 positions (MW=2). Deferred epilogue: per-lane raw max
// in 12 regs across the CTA's CONTIGUOUS tile range, flushed on sample
// change only. Staging: cp.async.bulk row copies (one per x row: VU*NSAMP
// ops/tile vs 850-6400 LDGSTS in r12-r14 — the staging ISSUE cost was the
// largest non-tensor term) tracked by a single mbarrier expect_tx; cvt is
// v-major (conflict-free scratch loads, 4-way fp16 stores).
// NTH=256 + MAXCTA=2 gives two independent CTAs/SM (protein).
// ---------------------------------------------------------------------------
template <int NTH, int GRID, int VU, int VPAD, int CHK, int TAPS, int LEN,
          int OUT, int SECT, int NSAMP, int NTPER, int FEAT_OFF, int XSTR,
          bool PRO>
__global__ __launch_bounds__(NTH, NTH == 256 ? 2 : 1)
void conv_mma(const float* __restrict__ x, const float* __restrict__ bias)
{
    constexpr int NW    = NTH / 32;
    constexpr int NPW   = NW / 2;                 // position-warps per group
    constexpr int NCF   = 6;                      // n8 channel-frags per warp
    constexpr int MW    = 2;
    constexpr int SW    = NPW / NSAMP;            // warps per section
    constexpr int TILE  = SW * 32;                // positions per section
    constexpr int ROWS  = NSAMP * SECT;
    constexpr int XROWS = ROWS + 8;               // zeroed halo rows
    constexpr int WSTR  = VPAD * TAPS * 2 + 16;   // 528
    constexpr int OFF_W = 0;
    constexpr int OFF_X = 96 * WSTR;              // 50688
    constexpr int XBUF  = XROWS * XSTR;
    constexpr int OFF_S = OFF_X + 2 * XBUF;       // fp32 scratch (16B-aligned)
    constexpr int SPITCH = ROWS;                  // %4==0 -> 16B-aligned rows
    constexpr int OFF_B = OFF_S + VU * SPITCH * 4;
    constexpr int OFF_M = OFF_B + 384;            // mbarrier (8B)
    constexpr int NTILES = (NSAMP == 2) ? BATCH / 2 : BATCH * NTPER;
    constexpr int TOTV  = VU * ROWS;
    constexpr int NCV   = (TOTV + NTH - 1) / NTH;

    extern __shared__ char sm[];
    const u32 sb  = sm32(sm);
    const int tid = threadIdx.x, wid = tid >> 5, lane = tid & 31;
    const int grp = wid / NPW, w = wid - grp * NPW;
    const int sect = w / SW, slot = w - sect * SW;
    const u32 mbar = sb + (u32)OFF_M;

    const __half* wsrc = PRO ? g_wP : g_wL;
    for (int u = tid; u < 96 * 256; u += NTH) {
        int c = u >> 8, k = u & 255;
        *(__half*)(sm + OFF_W + c * WSTR + k * 2) = wsrc[u];
    }
    // zero x region once (covers vocab pad bytes inside rows + halo rows)
    for (int u = tid; u < (2 * XBUF) / 16; u += NTH)
        *reinterpret_cast<float4*>(sm + OFF_X + u * 16) =
            make_float4(0.f, 0.f, 0.f, 0.f);
    if (tid < 96) ((float*)(sm + OFF_B))[tid] = bias[tid];
    if (tid == 0) mbar_init(mbar, 1);

    // contiguous tile range for this CTA
    constexpr int TPC = (NTILES + GRID - 1) / GRID;
    const int gbeg = blockIdx.x * TPC;
    const int gend = (gbeg + TPC < NTILES) ? gbeg + TPC : NTILES;
    if (gbeg >= gend) return;    // uniform per CTA

    // one bulk copy per x row; warp 0 only
    auto bulk_issue = [&](int g) {
        int b0 = (NSAMP == 2) ? 2 * g : g / NTPER;
        int t0 = (NSAMP == 2) ? 0 : (g - b0 * NTPER) * TILE;
        int valid = LEN - t0; if (valid > SECT) valid = SECT;
        u32 rbytes = (u32)(valid * 4);
        if (lane == 0) mbar_expect_tx(mbar, (u32)(VU * NSAMP) * rbytes);
        __syncwarp();
        for (int u = lane; u < VU * NSAMP; u += 32) {
            int v = u % VU, s = u / VU;
            bulk_g2s(sb + (u32)(OFF_S + (v * SPITCH + s * SECT) * 4),
                     x + ((size_t)(b0 + s) * VU + v) * LEN + t0,
                     rbytes, mbar);
        }
    };
    auto cvt = [&](int g, int nb) {
        int b0 = (NSAMP == 2) ? 2 * g : g / NTPER;
        int t0 = (NSAMP == 2) ? 0 : (g - b0 * NTPER) * TILE;
        int valid = LEN - t0; if (valid > SECT) valid = SECT;
        const float* sc = (const float*)(sm + OFF_S);
        char* xp = sm + OFF_X + nb * XBUF;
        #pragma unroll
        for (int i = 0; i < NCV; i++) {
            int u = tid + i * NTH;
            if (u < TOTV) {
                int v = u / ROWS, r = u - v * ROWS;   // v-major: cf loads
                int rr = r % SECT;
                float val = (rr < valid) ? sc[v * SPITCH + r] : 0.f;
                *(__half*)(xp + r * XSTR + v * 2) = __float2half_rn(val);
            }
        }
    };

    __syncthreads();                 // weights + mbar init visible
    if (wid == 0) bulk_issue(gbeg);
    mbar_wait(mbar, 0);
    __syncthreads();
    cvt(gbeg, 0);
    __syncthreads();
    u32 ph = 1;

    const u32 a_lo = (u32)((lane & 15) * XSTR + (lane >> 4) * 16);
    const u32 b_lo = (u32)(((lane & 7) + ((lane >> 4) << 3)) * WSTR
                           + ((lane >> 3) & 1) * 16);
    const u32 wb = sb + (u32)OFF_W + b_lo + (u32)(grp * 48 * WSTR);
    const int prow = sect * SECT + slot * 32;
    const float NEG = -1e30f;

    float mxv[12];
    #pragma unroll
    for (int q = 0; q < 12; q++) mxv[q] = NEG;

    auto flush = [&](int b) {
        #pragma unroll
        for (int off = 4; off <= 16; off <<= 1)
            #pragma unroll
            for (int q = 0; q < 12; q++)
                mxv[q] = fmaxf(mxv[q], __shfl_xor_sync(0xffffffffu, mxv[q], off));
        if (lane < 4) {
            #pragma unroll
            for (int j = 0; j < NCF; j++)
                #pragma unroll
                for (int e = 0; e < 2; e++) {
                    int c = grp * 48 + j * 8 + lane * 2 + e;
                    float bb = ((const float*)(sm + OFF_B))[c];
                    float val = fmaxf(mxv[2 * j + e] + bb, 0.f);
                    atomicMax(reinterpret_cast<int*>(
                                  &g_feat[(size_t)b * 192 + FEAT_OFF + c]),
                              __float_as_int(val));
                }
        }
        #pragma unroll
        for (int q = 0; q < 12; q++) mxv[q] = NEG;
    };

    int buf = 0;
    for (int g = gbeg; g < gend; ++g) {
        const int gn = g + 1;
        if (gn < gend && wid == 0) bulk_issue(gn);  // async under mma loop

        float acc[MW][NCF][4];
        #pragma unroll
        for (int m = 0; m < MW; m++)
            #pragma unroll
            for (int j = 0; j < NCF; j++)
                #pragma unroll
                for (int e = 0; e < 4; e++) acc[m][j][e] = 0.f;

        const u32 xab = sb + (u32)(OFF_X + buf * XBUF)
                      + (u32)prow * XSTR + a_lo;

        #pragma unroll
        for (int tap = 0; tap < TAPS; tap++) {
            #pragma unroll
            for (int ch = 0; ch < CHK; ch++) {
                const u32 aoff = (u32)(tap * XSTR + ch * 32);
                u32 ah[MW][4];
                #pragma unroll
                for (int m = 0; m < MW; m++)
                    ldsm4(ah[m], xab + aoff + (u32)(m * 16 * XSTR));
                const u32 wk = (u32)((tap * VPAD + ch * 16) * 2);
                #pragma unroll
                for (int p = 0; p < NCF / 2; p++) {
                    u32 bf[4];
                    ldsm4(bf, wb + (u32)(p * 16 * WSTR) + wk);
                    #pragma unroll
                    for (int m = 0; m < MW; m++) {
                        mma16816(acc[m][2 * p],     ah[m], bf[0], bf[1]);
                        mma16816(acc[m][2 * p + 1], ah[m], bf[2], bf[3]);
                    }
                }
            }
        }

        // ---- accumulate masked max into persistent regs; flush on b change
        {
            const int b0 = (NSAMP == 2) ? 2 * g : g / NTPER;
            const int t0 = (NSAMP == 2) ? 0 : (g - b0 * NTPER) * TILE;
            const int b  = b0 + ((NSAMP == 2) ? sect : 0);
            const int pb = ((NSAMP == 2) ? 0 : t0) + slot * 32;
            const int row = lane >> 2;
            #pragma unroll
            for (int m = 0; m < MW; m++) {
                const int p0 = pb + m * 16 + row;
                #pragma unroll
                for (int j = 0; j < NCF; j++)
                    #pragma unroll
                    for (int e = 0; e < 2; e++) {
                        float v = mxv[2 * j + e];
                        if (p0 < OUT)     v = fmaxf(v, acc[m][j][e]);
                        if (p0 + 8 < OUT) v = fmaxf(v, acc[m][j][e + 2]);
                        mxv[2 * j + e] = v;
                    }
            }
            bool bchange = (NSAMP == 2) || (gn >= gend)
                         || (gn / NTPER != g / NTPER);
            if (bchange) flush(b);
        }

        if (gn < gend) { mbar_wait(mbar, ph); ph ^= 1; }
        __syncthreads();                 // scratch ready + all mma reads done
        if (gn < gend) cvt(gn, buf ^ 1);
        __syncthreads();                 // buf^1 visible before next mma
        buf ^= 1;
    }
}

// ---------------------------------------------------------------------------
// Per-sample: x = feat.reshape(6,32); gram = x^T x; L2-normalize; dot w_aff.
// ---------------------------------------------------------------------------
__global__ __launch_bounds__(256)
void gram_readout_kernel(const float* __restrict__ w_aff,
                         const float* __restrict__ b_aff,
                         float* __restrict__ out, int B)
{
    __shared__ float s_w[1024];
    __shared__ float s_f[8][192];
    const int tid  = threadIdx.x;
    const int warp = tid >> 5, lane = tid & 31;
    const int b = blockIdx.x * 8 + warp;

    for (int u = tid; u < 1024; u += 256) s_w[u] = w_aff[u];
    if (b < B)
        for (int u = lane; u < 192; u += 32) s_f[warp][u] = g_feat[(size_t)b * 192 + u];
    __syncthreads();
    if (b >= B) return;

    float xk[6];
    #pragma unroll
    for (int i = 0; i < 6; i++) xk[i] = s_f[warp][i * 32 + lane];

    float s1 = 0.f, s2 = 0.f;
    #pragma unroll 4
    for (int j = 0; j < 32; j++) {
        float g = 0.f;
        #pragma unroll
        for (int i = 0; i < 6; i++) g = fmaf(s_f[warp][i * 32 + j], xk[i], g);
        s2 = fmaf(g, g, s2);
        s1 = fmaf(g, s_w[j * 32 + lane], s1);
    }
    #pragma unroll
    for (int off = 16; off > 0; off >>= 1) {
        s1 += __shfl_xor_sync(0xffffffffu, s1, off);
        s2 += __shfl_xor_sync(0xffffffffu, s2, off);
    }
    if (lane == 0) out[b] = s1 / (sqrtf(s2) + 1e-12f) + b_aff[0];
}

// ---------------------------------------------------------------------------

extern "C" void kernel_launch(void* const* d_in, const int* in_sizes, int n_in,
                              void* d_out, int out_size)
{
    const float* protein = (const float*)d_in[0];
    const float* ligand  = (const float*)d_in[1];
    const float* w_pro   = (const float*)d_in[2];
    const float* b_pro   = (const float*)d_in[3];
    const float* w_lig   = (const float*)d_in[4];
    const float* b_lig   = (const float*)d_in[5];
    const float* w_aff   = (const float*)d_in[6];
    const float* b_aff   = (const float*)d_in[7];

    int seen96 = 0;
    for (int i = 0; i < n_in; i++) {
        long long s = in_sizes[i];
        const float* p = (const float*)d_in[i];
        if      (s == (long long)BATCH * 25 * 1000) protein = p;
        else if (s == (long long)BATCH * 64 * 100)  ligand  = p;
        else if (s == 96LL * 25 * 8)                w_pro   = p;
        else if (s == 96LL * 64 * 4)                w_lig   = p;
        else if (s == 1024LL)                       w_aff   = p;
        else if (s == 96LL) { if (seen96++ == 0) b_pro = p; else b_lig = p; }
        else if (s == 1LL)                          b_aff   = p;
    }

    float* out = (float*)d_out;

    // ligand : 512thr grid 148, NSAMP=2 SECT=128, bulk staging (128 rows/tile)
    // protein: 256thr x 2 CTAs/SM (grid 296), TILE=128 NTPER=8 SECT=136,
    //          bulk staging (25 rows/tile), deferred flush per sample
    auto kL = conv_mma<512, 148, 64, 64, 4, 4, 100, 97, 128, 2, 1, 0, 144, false>;
    auto kP = conv_mma<256, 296, 25, 32, 2, 8, 1000, 993, 136, 1, 8, 96, 80, true>;

    // smem sizes (mirror kernel constexprs: OFF_M + 64)
    constexpr int SMEM_L = 50688 + 2 * (264 * 144) + 64 * 256 * 4 + 384 + 64;
    constexpr int SMEM_P = 50688 + 2 * (144 * 80)  + 25 * 136 * 4 + 384 + 64;

    cudaFuncSetAttribute(kL, cudaFuncAttributeMaxDynamicSharedMemorySize, SMEM_L);
    cudaFuncSetAttribute(kP, cudaFuncAttributeMaxDynamicSharedMemorySize, SMEM_P);

    zero_feat_kernel<<<(BATCH * 192 + 1023) / 1024, 1024>>>();
    prep_w<64, 4, 64, false><<<96, 256>>>(w_lig);
    prep_w<25, 8, 32, true><<<96, 256>>>(w_pro);
    kL<<<148, 512, SMEM_L>>>(ligand, b_lig);
    kP<<<296, 256, SMEM_P>>>(protein, b_pro);
    gram_readout_kernel<<<BATCH / 8, 256>>>(w_aff, b_aff, out, BATCH);
}

// round 16
// speedup vs baseline: 1.0770x; 1.0301x over previous
#include <cuda_runtime.h>
#include <cuda_fp16.h>
#include <math.h>

#define BATCH 4096
__device__ float g_feat[BATCH * 192];
// prepped fp16 weights: [c][k_lin], k_lin = tap*VPAD + v  (96 x 256 each)
__device__ __half g_wP[96 * 256], g_wL[96 * 256];

typedef unsigned int u32;

__device__ __forceinline__ u32 sm32(const void* p) {
    u32 a;
    asm("{ .reg .u64 t; cvta.to.shared.u64 t, %1; cvt.u32.u64 %0, t; }"
        : "=r"(a) : "l"(p));
    return a;
}
__device__ __forceinline__ void ldsm4(u32* r, u32 a) {
    asm volatile("ldmatrix.sync.aligned.m8n8.x4.shared.b16 {%0,%1,%2,%3}, [%4];"
                 : "=r"(r[0]), "=r"(r[1]), "=r"(r[2]), "=r"(r[3]) : "r"(a));
}
__device__ __forceinline__ void mma16816(float* d, const u32* a, u32 b0, u32 b1) {
    asm volatile(
        "mma.sync.aligned.m16n8k16.row.col.f32.f16.f16.f32 "
        "{%0,%1,%2,%3}, {%4,%5,%6,%7}, {%8,%9}, {%0,%1,%2,%3};"
        : "+f"(d[0]), "+f"(d[1]), "+f"(d[2]), "+f"(d[3])
        : "r"(a[0]), "r"(a[1]), "r"(a[2]), "r"(a[3]), "r"(b0), "r"(b1));
}
template <int BYTES>
__device__ __forceinline__ void cpB(u32 dst, const void* src) {
    asm volatile("cp.async.ca.shared.global [%0], [%1], %2;"
                 :: "r"(dst), "l"(src), "n"(BYTES));
}
__device__ __forceinline__ void cp_commit() {
    asm volatile("cp.async.commit_group;" ::: "memory");
}
__device__ __forceinline__ void cp_wait0() {
    asm volatile("cp.async.wait_group 0;" ::: "memory");
}
// --- sm_90-baseline bulk copy + mbarrier (legal on plain sm_100) ---
__device__ __forceinline__ void mbar_init(u32 mbar, u32 cnt) {
    asm volatile("mbarrier.init.shared.b64 [%0], %1;" :: "r"(mbar), "r"(cnt)
                 : "memory");
}
__device__ __forceinline__ void mbar_expect_tx(u32 mbar, u32 bytes) {
    asm volatile("mbarrier.arrive.expect_tx.shared.b64 _, [%0], %1;"
                 :: "r"(mbar), "r"(bytes) : "memory");
}
__device__ __forceinline__ void bulk_g2s(u32 dst, const void* src, u32 bytes,
                                         u32 mbar) {
    asm volatile(
        "cp.async.bulk.shared::cluster.global.mbarrier::complete_tx::bytes "
        "[%0], [%1], %2, [%3];"
        :: "r"(dst), "l"(src), "r"(bytes), "r"(mbar) : "memory");
}
__device__ __forceinline__ void mbar_wait(u32 mbar, u32 parity) {
    asm volatile(
        "{ .reg .pred P;\n"
        "WAITLP%=:\n"
        " mbarrier.try_wait.parity.acquire.cta.shared::cta.b64 P, [%0], %1, 0x989680;\n"
        " @P bra.uni WDONE%=;\n"
        " bra.uni WAITLP%=;\n"
        "WDONE%=: }"
        :: "r"(mbar), "r"(parity) : "memory");
}

// ---------------------------------------------------------------------------
// weight prep: fp32 [96][VU][TAPS] -> fp16 [96][256], k_lin = tap*VPAD + v
// ---------------------------------------------------------------------------
template <int VU, int TAPS, int VPAD, bool PRO>
__global__ void prep_w(const float* __restrict__ w) {
    int u = blockIdx.x * 256 + threadIdx.x;
    if (u >= 96 * 256) return;
    int c = u >> 8, k = u & 255;
    int tap = k / VPAD, v = k - tap * VPAD;
    float val = (v < VU) ? w[(c * VU + v) * TAPS + tap] : 0.f;
    (PRO ? g_wP : g_wL)[u] = __float2half_rn(val);
}

__global__ void zero_feat_kernel() {
    int i = blockIdx.x * 1024 + threadIdx.x;
    if (i < BATCH * 192) g_feat[i] = 0.f;
}

// ---------------------------------------------------------------------------
// Persistent conv via mma.sync m16n8k16 fp16 (x, w fp16; rel_err ~4e-5).
// NTH threads = NW warps = 2 channel-groups (grp, 48 ch each, NCF=6) x NPW
// position-warps; sect = w/SW selects the sample section (SW = NPW/NSAMP);
// each warp owns 32 positions (MW=2). Deferred epilogue: per-lane raw max
// in 12 regs across the CTA's CONTIGUOUS tile range, flushed on sample
// change only. Staging is per-branch (r15/r16 measured):
//   BULK=true  (protein, few long rows): cp.async.bulk per row + mbarrier;
//              SPITCH=ROWS (16B-aligned); v-major cvt.
//   BULK=false (ligand, many short rows): LDGSTS CPB=8, SPITCH=ROWS+2,
//              r-major cvt (conflict-free stores, 2-way loads).
// NTH=256 + MAXCTA=2 gives two independent CTAs/SM (protein).
// ---------------------------------------------------------------------------
template <int NTH, int GRID, int VU, int VPAD, int CHK, int TAPS, int LEN,
          int OUT, int SECT, int NSAMP, int NTPER, int FEAT_OFF, int XSTR,
          bool BULK, bool PRO>
__global__ __launch_bounds__(NTH, NTH == 256 ? 2 : 1)
void conv_mma(const float* __restrict__ x, const float* __restrict__ bias)
{
    constexpr int NW    = NTH / 32;
    constexpr int NPW   = NW / 2;                 // position-warps per group
    constexpr int NCF   = 6;                      // n8 channel-frags per warp
    constexpr int MW    = 2;
    constexpr int SW    = NPW / NSAMP;            // warps per section
    constexpr int TILE  = SW * 32;                // positions per section
    constexpr int ROWS  = NSAMP * SECT;
    constexpr int XROWS = ROWS + 8;               // zeroed halo rows
    constexpr int WSTR  = VPAD * TAPS * 2 + 16;   // 528
    constexpr int OFF_W = 0;
    constexpr int OFF_X = 96 * WSTR;              // 50688
    constexpr int XBUF  = XROWS * XSTR;
    constexpr int OFF_S = OFF_X + 2 * XBUF;       // fp32 scratch (16B-aligned)
    constexpr int SPITCH = BULK ? ROWS : ((ROWS + 2) & ~1);
    constexpr int OFF_B = OFF_S + VU * SPITCH * 4;
    constexpr int OFF_M = OFF_B + 384;            // mbarrier (8B)
    constexpr int NTILES = (NSAMP == 2) ? BATCH / 2 : BATCH * NTPER;
    constexpr int CPBY  = 8;                      // LDGSTS chunk bytes
    constexpr int CELEM = CPBY / 4;
    constexpr int NCHK  = SECT / CELEM;
    constexpr int TOTC  = VU * NSAMP * NCHK;
    constexpr int NCP   = (TOTC + NTH - 1) / NTH;
    constexpr int TOTV  = VU * ROWS;
    constexpr int NCV   = (TOTV + NTH - 1) / NTH;

    extern __shared__ char sm[];
    const u32 sb  = sm32(sm);
    const int tid = threadIdx.x, wid = tid >> 5, lane = tid & 31;
    const int grp = wid / NPW, w = wid - grp * NPW;
    const int sect = w / SW, slot = w - sect * SW;
    const u32 mbar = sb + (u32)OFF_M;

    const __half* wsrc = PRO ? g_wP : g_wL;
    for (int u = tid; u < 96 * 256; u += NTH) {
        int c = u >> 8, k = u & 255;
        *(__half*)(sm + OFF_W + c * WSTR + k * 2) = wsrc[u];
    }
    // zero x region once (covers vocab pad bytes inside rows + halo rows)
    for (int u = tid; u < (2 * XBUF) / 16; u += NTH)
        *reinterpret_cast<float4*>(sm + OFF_X + u * 16) =
            make_float4(0.f, 0.f, 0.f, 0.f);
    if (tid < 96) ((float*)(sm + OFF_B))[tid] = bias[tid];
    if (BULK && tid == 0) mbar_init(mbar, 1);

    // contiguous tile range for this CTA
    constexpr int TPC = (NTILES + GRID - 1) / GRID;
    const int gbeg = blockIdx.x * TPC;
    const int gend = (gbeg + TPC < NTILES) ? gbeg + TPC : NTILES;
    if (gbeg >= gend) return;    // uniform per CTA

    // BULK path: one bulk copy per x row (warp 0 only)
    auto bulk_issue = [&](int g) {
        int b0 = (NSAMP == 2) ? 2 * g : g / NTPER;
        int t0 = (NSAMP == 2) ? 0 : (g - b0 * NTPER) * TILE;
        int valid = LEN - t0; if (valid > SECT) valid = SECT;
        u32 rbytes = (u32)(valid * 4);
        if (lane == 0) mbar_expect_tx(mbar, (u32)(VU * NSAMP) * rbytes);
        __syncwarp();
        for (int u = lane; u < VU * NSAMP; u += 32) {
            int v = u % VU, s = u / VU;
            bulk_g2s(sb + (u32)(OFF_S + (v * SPITCH + s * SECT) * 4),
                     x + ((size_t)(b0 + s) * VU + v) * LEN + t0,
                     rbytes, mbar);
        }
    };
    // LDGSTS path: CPB=8 chunks, all threads
    auto ldgsts_issue = [&](int g) {
        int b0 = (NSAMP == 2) ? 2 * g : g / NTPER;
        int t0 = (NSAMP == 2) ? 0 : (g - b0 * NTPER) * TILE;
        int valid = LEN - t0; if (valid > SECT) valid = SECT;
        int nch = valid / CELEM;
        #pragma unroll
        for (int i = 0; i < NCP; i++) {
            int u = tid + i * NTH;
            if (u < TOTC) {
                int v = u / (NSAMP * NCHK);
                int rem = u - v * (NSAMP * NCHK);
                int s = rem / NCHK, c = rem - s * NCHK;
                if (c < nch)
                    cpB<CPBY>(sb + (u32)(OFF_S +
                                  (v * SPITCH + s * SECT + c * CELEM) * 4),
                              x + ((size_t)(b0 + s) * VU + v) * LEN
                                + t0 + c * CELEM);
            }
        }
        cp_commit();
    };
    auto cvt = [&](int g, int nb) {
        int b0 = (NSAMP == 2) ? 2 * g : g / NTPER;
        int t0 = (NSAMP == 2) ? 0 : (g - b0 * NTPER) * TILE;
        int valid = LEN - t0; if (valid > SECT) valid = SECT;
        const float* sc = (const float*)(sm + OFF_S);
        char* xp = sm + OFF_X + nb * XBUF;
        #pragma unroll
        for (int i = 0; i < NCV; i++) {
            int u = tid + i * NTH;
            if (u < TOTV) {
                int v, r;
                if (BULK) { v = u / ROWS; r = u - v * ROWS; }   // cf loads
                else      { r = u / VU;   v = u - r * VU;   }   // cf stores
                int rr = r % SECT;
                float val = (rr < valid) ? sc[v * SPITCH + r] : 0.f;
                *(__half*)(xp + r * XSTR + v * 2) = __float2half_rn(val);
            }
        }
    };

    __syncthreads();                 // weights + mbar init visible
    if (BULK) {
        if (wid == 0) bulk_issue(gbeg);
        mbar_wait(mbar, 0);
    } else {
        ldgsts_issue(gbeg);
        cp_wait0();
    }
    __syncthreads();
    cvt(gbeg, 0);
    __syncthreads();
    u32 ph = 1;

    const u32 a_lo = (u32)((lane & 15) * XSTR + (lane >> 4) * 16);
    const u32 b_lo = (u32)(((lane & 7) + ((lane >> 4) << 3)) * WSTR
                           + ((lane >> 3) & 1) * 16);
    const u32 wb = sb + (u32)OFF_W + b_lo + (u32)(grp * 48 * WSTR);
    const int prow = sect * SECT + slot * 32;
    const float NEG = -1e30f;

    float mxv[12];
    #pragma unroll
    for (int q = 0; q < 12; q++) mxv[q] = NEG;

    auto flush = [&](int b) {
        #pragma unroll
        for (int off = 4; off <= 16; off <<= 1)
            #pragma unroll
            for (int q = 0; q < 12; q++)
                mxv[q] = fmaxf(mxv[q], __shfl_xor_sync(0xffffffffu, mxv[q], off));
        if (lane < 4) {
            #pragma unroll
            for (int j = 0; j < NCF; j++)
                #pragma unroll
                for (int e = 0; e < 2; e++) {
                    int c = grp * 48 + j * 8 + lane * 2 + e;
                    float bb = ((const float*)(sm + OFF_B))[c];
                    float val = fmaxf(mxv[2 * j + e] + bb, 0.f);
                    atomicMax(reinterpret_cast<int*>(
                                  &g_feat[(size_t)b * 192 + FEAT_OFF + c]),
                              __float_as_int(val));
                }
        }
        #pragma unroll
        for (int q = 0; q < 12; q++) mxv[q] = NEG;
    };

    int buf = 0;
    for (int g = gbeg; g < gend; ++g) {
        const int gn = g + 1;
        if (gn < gend) {                 // async: overlaps the mma loop
            if (BULK) { if (wid == 0) bulk_issue(gn); }
            else      ldgsts_issue(gn);
        }

        float acc[MW][NCF][4];
        #pragma unroll
        for (int m = 0; m < MW; m++)
            #pragma unroll
            for (int j = 0; j < NCF; j++)
                #pragma unroll
                for (int e = 0; e < 4; e++) acc[m][j][e] = 0.f;

        const u32 xab = sb + (u32)(OFF_X + buf * XBUF)
                      + (u32)prow * XSTR + a_lo;

        #pragma unroll
        for (int tap = 0; tap < TAPS; tap++) {
            #pragma unroll
            for (int ch = 0; ch < CHK; ch++) {
                const u32 aoff = (u32)(tap * XSTR + ch * 32);
                u32 ah[MW][4];
                #pragma unroll
                for (int m = 0; m < MW; m++)
                    ldsm4(ah[m], xab + aoff + (u32)(m * 16 * XSTR));
                const u32 wk = (u32)((tap * VPAD + ch * 16) * 2);
                #pragma unroll
                for (int p = 0; p < NCF / 2; p++) {
                    u32 bf[4];
                    ldsm4(bf, wb + (u32)(p * 16 * WSTR) + wk);
                    #pragma unroll
                    for (int m = 0; m < MW; m++) {
                        mma16816(acc[m][2 * p],     ah[m], bf[0], bf[1]);
                        mma16816(acc[m][2 * p + 1], ah[m], bf[2], bf[3]);
                    }
                }
            }
        }

        // ---- accumulate masked max into persistent regs; flush on b change
        {
            const int b0 = (NSAMP == 2) ? 2 * g : g / NTPER;
            const int t0 = (NSAMP == 2) ? 0 : (g - b0 * NTPER) * TILE;
            const int b  = b0 + ((NSAMP == 2) ? sect : 0);
            const int pb = ((NSAMP == 2) ? 0 : t0) + slot * 32;
            const int row = lane >> 2;
            #pragma unroll
            for (int m = 0; m < MW; m++) {
                const int p0 = pb + m * 16 + row;
                #pragma unroll
                for (int j = 0; j < NCF; j++)
                    #pragma unroll
                    for (int e = 0; e < 2; e++) {
                        float v = mxv[2 * j + e];
                        if (p0 < OUT)     v = fmaxf(v, acc[m][j][e]);
                        if (p0 + 8 < OUT) v = fmaxf(v, acc[m][j][e + 2]);
                        mxv[2 * j + e] = v;
                    }
            }
            bool bchange = (NSAMP == 2) || (gn >= gend)
                         || (gn / NTPER != g / NTPER);
            if (bchange) flush(b);
        }

        if (gn < gend) {
            if (BULK) { mbar_wait(mbar, ph); ph ^= 1; }
            else      cp_wait0();
        }
        __syncthreads();                 // scratch ready + all mma reads done
        if (gn < gend) cvt(gn, buf ^ 1);
        __syncthreads();                 // buf^1 visible before next mma
        buf ^= 1;
    }
}

// ---------------------------------------------------------------------------
// Per-sample: x = feat.reshape(6,32); gram = x^T x; L2-normalize; dot w_aff.
// ---------------------------------------------------------------------------
__global__ __launch_bounds__(256)
void gram_readout_kernel(const float* __restrict__ w_aff,
                         const float* __restrict__ b_aff,
                         float* __restrict__ out, int B)
{
    __shared__ float s_w[1024];
    __shared__ float s_f[8][192];
    const int tid  = threadIdx.x;
    const int warp = tid >> 5, lane = tid & 31;
    const int b = blockIdx.x * 8 + warp;

    for (int u = tid; u < 1024; u += 256) s_w[u] = w_aff[u];
    if (b < B)
        for (int u = lane; u < 192; u += 32) s_f[warp][u] = g_feat[(size_t)b * 192 + u];
    __syncthreads();
    if (b >= B) return;

    float xk[6];
    #pragma unroll
    for (int i = 0; i < 6; i++) xk[i] = s_f[warp][i * 32 + lane];

    float s1 = 0.f, s2 = 0.f;
    #pragma unroll 4
    for (int j = 0; j < 32; j++) {
        float g = 0.f;
        #pragma unroll
        for (int i = 0; i < 6; i++) g = fmaf(s_f[warp][i * 32 + j], xk[i], g);
        s2 = fmaf(g, g, s2);
        s1 = fmaf(g, s_w[j * 32 + lane], s1);
    }
    #pragma unroll
    for (int off = 16; off > 0; off >>= 1) {
        s1 += __shfl_xor_sync(0xffffffffu, s1, off);
        s2 += __shfl_xor_sync(0xffffffffu, s2, off);
    }
    if (lane == 0) out[b] = s1 / (sqrtf(s2) + 1e-12f) + b_aff[0];
}

// ---------------------------------------------------------------------------

extern "C" void kernel_launch(void* const* d_in, const int* in_sizes, int n_in,
                              void* d_out, int out_size)
{
    const float* protein = (const float*)d_in[0];
    const float* ligand  = (const float*)d_in[1];
    const float* w_pro   = (const float*)d_in[2];
    const float* b_pro   = (const float*)d_in[3];
    const float* w_lig   = (const float*)d_in[4];
    const float* b_lig   = (const float*)d_in[5];
    const float* w_aff   = (const float*)d_in[6];
    const float* b_aff   = (const float*)d_in[7];

    int seen96 = 0;
    for (int i = 0; i < n_in; i++) {
        long long s = in_sizes[i];
        const float* p = (const float*)d_in[i];
        if      (s == (long long)BATCH * 25 * 1000) protein = p;
        else if (s == (long long)BATCH * 64 * 100)  ligand  = p;
        else if (s == 96LL * 25 * 8)                w_pro   = p;
        else if (s == 96LL * 64 * 4)                w_lig   = p;
        else if (s == 1024LL)                       w_aff   = p;
        else if (s == 96LL) { if (seen96++ == 0) b_pro = p; else b_lig = p; }
        else if (s == 1LL)                          b_aff   = p;
    }

    float* out = (float*)d_out;

    // ligand : r12 staging (LDGSTS CPB=8, r-major cvt) — measured best 98.7us
    // protein: r15 staging (bulk rows + mbarrier) — measured best
    auto kL = conv_mma<512, 148, 64, 64, 4, 4, 100, 97, 128, 2, 1, 0, 144,
                       false, false>;
    auto kP = conv_mma<256, 296, 25, 32, 2, 8, 1000, 993, 136, 1, 8, 96, 80,
                       true, true>;

    // smem sizes (mirror kernel constexprs: OFF_M + 64)
    constexpr int SMEM_L = 50688 + 2 * (264 * 144) + 64 * 258 * 4 + 384 + 64;
    constexpr int SMEM_P = 50688 + 2 * (144 * 80)  + 25 * 136 * 4 + 384 + 64;

    cudaFuncSetAttribute(kL, cudaFuncAttributeMaxDynamicSharedMemorySize, SMEM_L);
    cudaFuncSetAttribute(kP, cudaFuncAttributeMaxDynamicSharedMemorySize, SMEM_P);

    zero_feat_kernel<<<(BATCH * 192 + 1023) / 1024, 1024>>>();
    prep_w<64, 4, 64, false><<<96, 256>>>(w_lig);
    prep_w<25, 8, 32, true><<<96, 256>>>(w_pro);
    kL<<<148, 512, SMEM_L>>>(ligand, b_lig);
    kP<<<296, 256, SMEM_P>>>(protein, b_pro);
    gram_readout_kernel<<<BATCH / 8, 256>>>(w_aff, b_aff, out, BATCH);
}